// round 15
// baseline (speedup 1.0000x reference)
#include <cuda_runtime.h>
#include <math.h>

#define NS_ITERS 3
#define JAC_SWEEPS 5

// ---------------- device scratch (no allocations allowed) ----------------
__device__ float g_rel[256];            // 16x16 isometry
__device__ float g_W[256];              // expm(-sym(bias_spd)/2)
__device__ float g_Ybg[400];            // cayley(bias_gr) 20x20

// =====================================================================
// warp-level 16x16 helpers. Layout: lane = 2*r + cpar, lane owns row r,
// cols c0..c0+7 (c0 = cpar*8). Smem tiles row-major, stride 20 floats.
// =====================================================================
__device__ __forceinline__ void fullrow16(const float h[8], int cpar, float a[16]) {
    #pragma unroll
    for (int i = 0; i < 8; i++) {
        float o = __shfl_xor_sync(0xffffffffu, h[i], 1);
        a[i]     = cpar ? o    : h[i];
        a[8 + i] = cpar ? h[i] : o;
    }
}

// C(half-row) = a(full row) @ B(smem, stride 20)
__device__ __forceinline__ void wmm16(const float a[16], const float* Bs, int c0, float c[8]) {
    #pragma unroll
    for (int i = 0; i < 8; i++) c[i] = 0.f;
    #pragma unroll
    for (int k = 0; k < 16; k++) {
        float4 b0 = *(const float4*)(Bs + k * 20 + c0);
        float4 b1 = *(const float4*)(Bs + k * 20 + c0 + 4);
        float ak = a[k];
        c[0] += ak * b0.x; c[1] += ak * b0.y; c[2] += ak * b0.z; c[3] += ak * b0.w;
        c[4] += ak * b1.x; c[5] += ak * b1.y; c[6] += ak * b1.z; c[7] += ak * b1.w;
    }
}

// C(half-row) = a(full row) @ B^T (B rows in smem, stride 20)
__device__ __forceinline__ void wmm16t(const float a[16], const float* Bs, int c0, float c[8]) {
    #pragma unroll
    for (int i = 0; i < 8; i++) {
        const float* br = Bs + (c0 + i) * 20;
        float4 b0 = *(const float4*)(br);
        float4 b1 = *(const float4*)(br + 4);
        float4 b2 = *(const float4*)(br + 8);
        float4 b3 = *(const float4*)(br + 12);
        c[i] = a[0]*b0.x + a[1]*b0.y + a[2]*b0.z + a[3]*b0.w
             + a[4]*b1.x + a[5]*b1.y + a[6]*b1.z + a[7]*b1.w
             + a[8]*b2.x + a[9]*b2.y + a[10]*b2.z + a[11]*b2.w
             + a[12]*b3.x + a[13]*b3.y + a[14]*b3.z + a[15]*b3.w;
    }
}

__device__ __forceinline__ void stoh(float* Bs, int r, int c0, const float h[8]) {
    *(float4*)(Bs + r * 20 + c0)     = make_float4(h[0], h[1], h[2], h[3]);
    *(float4*)(Bs + r * 20 + c0 + 4) = make_float4(h[4], h[5], h[6], h[7]);
}

// =====================================================================
// Kernel 0: one-block precompute of batch-invariant matrices (proven)
// =====================================================================
__global__ void precompute_kernel(const float* __restrict__ ref_params,
                                  const float* __restrict__ bias_spd,
                                  const float* __restrict__ bias_gr)
{
    __shared__ float Bs[256], E[256];
    __shared__ float A20[400];
    __shared__ float Aug[20][40];
    __shared__ float prow[40], fcol[20];
    __shared__ float pv;

    const int tid = threadIdx.x;
    const int i = tid >> 4, j = tid & 15;

    // ---- rel = prod of 120 Givens rotations, each lane owns one row ----
    if (tid < 16) {
        float row[16];
        #pragma unroll
        for (int c = 0; c < 16; c++) row[c] = (c == tid) ? 1.f : 0.f;
        int m = 0;
        for (int pi = 0; pi < 16; pi++) {
            for (int pj = pi + 1; pj < 16; pj++) {
                float ang = ref_params[m++];
                float c = cosf(ang), s = sinf(ang);
                float a = row[pi], b = row[pj];
                row[pi] = c * a + s * b;
                row[pj] = -s * a + c * b;
            }
        }
        #pragma unroll
        for (int c = 0; c < 16; c++) g_rel[tid * 16 + c] = row[c];
    }

    // ---- W = expm(-0.25*(bias+bias^T)) via scaling(2^-7) + Taylor-8 ----
    {
        float v = -0.25f * (bias_spd[i * 16 + j] + bias_spd[j * 16 + i]);
        Bs[tid] = v * (1.0f / 128.0f);
        E[tid]  = (i == j) ? 1.f : 0.f;
    }
    __syncthreads();
    for (int k = 8; k >= 1; k--) {
        float a = 0.f;
        #pragma unroll
        for (int kk = 0; kk < 16; kk++) a += Bs[i * 16 + kk] * E[kk * 16 + j];
        __syncthreads();
        E[tid] = ((i == j) ? 1.f : 0.f) + a * (1.0f / (float)k);
        __syncthreads();
    }
    for (int q = 0; q < 7; q++) {
        float a = 0.f;
        #pragma unroll
        for (int kk = 0; kk < 16; kk++) a += E[i * 16 + kk] * E[kk * 16 + j];
        __syncthreads();
        E[tid] = a;
        __syncthreads();
    }
    g_W[tid] = E[tid];

    // ---- Ybg = (I - A)(I + A)^{-1}, A = skew(bias_gr) 20x20 ----
    for (int e = tid; e < 400; e += 256) {
        int ii = e / 20, jj = e % 20;
        float v = 0.f;
        if (ii < 10 && jj >= 10)      v =  bias_gr[ii * 10 + (jj - 10)];
        else if (ii >= 10 && jj < 10) v = -bias_gr[jj * 10 + (ii - 10)];
        A20[e] = v;
    }
    __syncthreads();
    for (int e = tid; e < 800; e += 256) {
        int ii = e / 40, jj = e % 40;
        float v;
        if (jj < 20) v = ((ii == jj) ? 1.f : 0.f) + A20[ii * 20 + jj];
        else         v = ((jj - 20) == ii) ? 1.f : 0.f;
        Aug[ii][jj] = v;
    }
    __syncthreads();
    for (int p = 0; p < 20; p++) {
        if (tid == 0) pv = Aug[p][p];
        __syncthreads();
        if (tid < 40) prow[tid] = Aug[p][tid] / pv;
        if (tid >= 64 && tid < 84) {
            int r = tid - 64;
            fcol[r] = (r == p) ? 0.f : Aug[r][p];
        }
        __syncthreads();
        for (int e = tid; e < 800; e += 256) {
            int ii = e / 40, jj = e % 40;
            Aug[ii][jj] = (ii == p) ? prow[jj] : Aug[ii][jj] - fcol[ii] * prow[jj];
        }
        __syncthreads();
    }
    for (int e = tid; e < 400; e += 256) {
        int ii = e / 20, jj = e % 20;
        float a = 0.f;
        #pragma unroll
        for (int k = 0; k < 20; k++) {
            float l = ((ii == k) ? 1.f : 0.f) - A20[ii * 20 + k];
            a += l * Aug[k][jj + 20];
        }
        g_Ybg[e] = a;
    }
}

// =====================================================================
// Fused kernel: grid = B, block = 64 (2 warps per batch element).
//   warp0: SPD q-chain (P init = Rel)  ->  NS inv-sqrt -> m -> Jacobi -> dspd
//   warp1: SPD a-chain -> Xa to smem  ->  GR chain (both tables) -> dgr
// Chains use token QUADS with Taylor-2 on the quad sum:
//   factor = I + S + S^2/2, S = sum of 4 token tangents (commutator-only error).
// =====================================================================
__global__ void __launch_bounds__(64, 8)
fused_kernel(const int* __restrict__ q_ids, const int* __restrict__ a_ids,
             const float* __restrict__ q_emb_spd, const float* __restrict__ a_emb_spd,
             const float* __restrict__ q_emb_gr, const float* __restrict__ a_emb_gr,
             const float* __restrict__ trans,
             const float* __restrict__ wf, const float* __restrict__ wb,
             float* __restrict__ out, int B, int T)
{
    __shared__ float buf0[640], buf1[640];
    __shared__ float XaS[320];
    __shared__ float RelS[320], WS[320];
    __shared__ float YbgT[400], transS[100];
    __shared__ float dgr_s;

    const int tid = threadIdx.x;
    for (int e = tid; e < 256; e += 64) {
        RelS[(e >> 4) * 20 + (e & 15)] = g_rel[e];
        WS  [(e >> 4) * 20 + (e & 15)] = g_W[e];
    }
    for (int e = tid; e < 400; e += 64) {
        int ii = e / 20, kk = e - ii * 20;
        YbgT[kk * 20 + ii] = g_Ybg[e];
    }
    for (int e = tid; e < 100; e += 64) transS[e] = trans[e];
    __syncthreads();

    const int w = tid >> 5, lane = tid & 31;
    const int b = blockIdx.x;
    const int r = lane >> 1, cpar = lane & 1, c0 = cpar * 8;
    float* bufA = w ? buf1 : buf0;
    float* bufB = bufA + 320;

    // =============== phase 1: SPD chain, table = w ===============
    const int* ids = w ? a_ids : q_ids;
    const float* emb = w ? a_emb_spd : q_emb_spd;

    float P[8];
    if (w == 0) {
        #pragma unroll
        for (int i = 0; i < 8; i++) P[i] = RelS[r * 20 + c0 + i];   // P = Rel
    } else {
        #pragma unroll
        for (int i = 0; i < 8; i++) P[i] = ((r >> 3) == cpar && (r & 7) == i) ? 1.f : 0.f;
    }

    const int nmid = T - 1;
    #pragma unroll 1
    for (int t = 0; t < nmid; t += 4) {
        float er[8] = {0.f,0.f,0.f,0.f,0.f,0.f,0.f,0.f};
        #pragma unroll
        for (int s = 0; s < 4; s++) {
            int tt = t + s;
            if (tt < nmid) {
                int id = ids[b * T + tt];
                const float* rp = emb + (size_t)id * 256 + r * 16 + c0;
                float4 e0 = *(const float4*)rp;
                float4 e1 = *(const float4*)(rp + 4);
                er[0]+=e0.x; er[1]+=e0.y; er[2]+=e0.z; er[3]+=e0.w;
                er[4]+=e1.x; er[5]+=e1.y; er[6]+=e1.z; er[7]+=e1.w;
            }
        }
        __syncwarp();                                  // prior-iter buf reads done
        stoh(bufA, r, c0, er);
        __syncwarp();                                  // Esum visible
        float Ah[8];
        #pragma unroll
        for (int i = 0; i < 8; i++) Ah[i] = 0.25f * (er[i] + bufA[(c0 + i) * 20 + r]);
        stoh(bufB, r, c0, Ah);
        __syncwarp();                                  // S visible
        float a16[16]; fullrow16(Ah, cpar, a16);
        float S2[8];  wmm16(a16, bufB, c0, S2);        // S @ S
        float Sm[8];
        #pragma unroll
        for (int i = 0; i < 8; i++) Sm[i] = Ah[i] + 0.5f * S2[i];
        if ((r >> 3) == cpar) Sm[r & 7] += 1.f;        // I + S + S^2/2
        __syncwarp();                                  // S reads done
        stoh(bufB, r, c0, Sm);
        __syncwarp();                                  // Sm visible
        float p16[16]; fullrow16(P, cpar, p16);
        float PA[8];  wmm16(p16, bufB, c0, PA);        // P @ Sm
        #pragma unroll
        for (int i = 0; i < 8; i++) P[i] = PA[i];
    }

    // last token: Exp = I + A + A^2/2, Y = P @ Exp @ P^T
    float Y[8];
    {
        int id = ids[b * T + (T - 1)];
        const float* rp = emb + (size_t)id * 256 + r * 16 + c0;
        float4 e0 = *(const float4*)rp;
        float4 e1 = *(const float4*)(rp + 4);
        __syncwarp();
        *(float4*)(bufA + r * 20 + c0)     = e0;
        *(float4*)(bufA + r * 20 + c0 + 4) = e1;
        __syncwarp();
        float el[8] = {e0.x, e0.y, e0.z, e0.w, e1.x, e1.y, e1.z, e1.w};
        float Ah[8];
        #pragma unroll
        for (int i = 0; i < 8; i++) Ah[i] = 0.5f * (el[i] + bufA[(c0 + i) * 20 + r]);
        stoh(bufB, r, c0, Ah);
        __syncwarp();
        float a16[16]; fullrow16(Ah, cpar, a16);
        float A2[8];  wmm16(a16, bufB, c0, A2);
        float Sm[8];
        #pragma unroll
        for (int i = 0; i < 8; i++) Sm[i] = Ah[i] + 0.5f * A2[i];
        if ((r >> 3) == cpar) Sm[r & 7] += 1.f;
        __syncwarp();
        stoh(bufB, r, c0, Sm);
        stoh(bufA, r, c0, P);                          // stash P for transpose
        __syncwarp();
        float p16[16]; fullrow16(P, cpar, p16);
        float Pn[8];  wmm16(p16, bufB, c0, Pn);        // P @ Exp
        float t16[16]; fullrow16(Pn, cpar, t16);
        wmm16t(t16, bufA, c0, Y);                      // @ P^T
    }
    if (w == 1) stoh(XaS, r, c0, Y);                   // publish Xa
    __syncthreads();                                   // ---- phase boundary ----

    // =============== phase 2 ===============
    float dspd = 0.f;
    if (w == 0) {
        // ---- Newton-Schulz: Z -> X^{-1/2}  (X = Y, already rel-conjugated) ----
        float Z[8];
        #pragma unroll
        for (int i = 0; i < 8; i++) Z[i] = ((r >> 3) == cpar && (r & 7) == i) ? 1.f : 0.f;
        #pragma unroll 1
        for (int it = 0; it < NS_ITERS; it++) {
            __syncwarp(); stoh(bufA, r, c0, Y); __syncwarp();
            float z16[16]; fullrow16(Z, cpar, z16);
            float G[8];   wmm16(z16, bufA, c0, G);      // Z@Y
            #pragma unroll
            for (int i = 0; i < 8; i++) G[i] = -0.5f * G[i];
            if ((r >> 3) == cpar) G[r & 7] += 1.5f;
            __syncwarp(); stoh(bufB, r, c0, G); __syncwarp();
            float y16[16]; fullrow16(Y, cpar, y16);
            float Yn[8];  wmm16(y16, bufB, c0, Yn);     // Y@G
            __syncwarp(); stoh(bufA, r, c0, Z); __syncwarp();
            float g16[16]; fullrow16(G, cpar, g16);
            float Zn[8];  wmm16(g16, bufA, c0, Zn);     // G@Z
            #pragma unroll
            for (int i = 0; i < 8; i++) { Y[i] = Yn[i]; Z[i] = Zn[i]; }
        }

        // ---- m = C @ Xa @ C^T, C = W@Z (W,Z symmetric) ----
        __syncwarp(); stoh(bufA, r, c0, Z); __syncwarp();
        {
            const float* wr = WS + r * 20;
            float4 w0 = *(const float4*)wr,       w1 = *(const float4*)(wr + 4),
                   w2 = *(const float4*)(wr + 8), w3 = *(const float4*)(wr + 12);
            float wrow[16] = {w0.x,w0.y,w0.z,w0.w, w1.x,w1.y,w1.z,w1.w,
                              w2.x,w2.y,w2.z,w2.w, w3.x,w3.y,w3.z,w3.w};
            float Ch[8]; wmm16(wrow, bufA, c0, Ch);     // C = W@Z
            __syncwarp(); stoh(bufB, r, c0, Ch); __syncwarp();
            float c16[16]; fullrow16(Ch, cpar, c16);
            float T1[8]; wmm16(c16, XaS, c0, T1);       // C@Xa
            float t16[16]; fullrow16(T1, cpar, t16);
            float Mh[8]; wmm16t(t16, bufB, c0, Mh);     // @C^T
            __syncwarp(); stoh(bufA, r, c0, Mh); __syncwarp();
        }

        // ---- shfl-resident Jacobi (rows in registers) ----
        const int jr = lane & 15;
        float a[16];
        {
            const float* rp = bufA + jr * 20;
            float4 v0 = *(const float4*)rp,        v1 = *(const float4*)(rp + 4),
                   v2 = *(const float4*)(rp + 8),  v3 = *(const float4*)(rp + 12);
            a[0]=v0.x; a[1]=v0.y; a[2]=v0.z; a[3]=v0.w;
            a[4]=v1.x; a[5]=v1.y; a[6]=v1.z; a[7]=v1.w;
            a[8]=v2.x; a[9]=v2.y; a[10]=v2.z; a[11]=v2.w;
            a[12]=v3.x; a[13]=v3.y; a[14]=v3.z; a[15]=v3.w;
        }
        #pragma unroll 1
        for (int sweep = 0; sweep < JAC_SWEEPS; sweep++) {
            #pragma unroll
            for (int rr = 0; rr < 15; rr++) {
                int u  = (jr == 0) ? 15 : (jr - 1 - rr + 30) % 15;
                int pu = (u == 15) ? 14 : ((u == 14) ? 15 : 13 - u);
                int partner = (pu == 15) ? 0 : 1 + ((pu + rr) % 15);
                bool isp = (jr == 0) || (u <= 6);
                float mydiag = 0.f, across = 0.f;
                #pragma unroll
                for (int i = 0; i < 16; i++) {
                    if (i == jr)      mydiag = a[i];
                    if (i == partner) across = a[i];
                }
                float partdiag = __shfl_sync(0xffffffffu, mydiag, partner);
                float cc, ss;
                if (fabsf(across) < 1e-30f) { cc = 1.f; ss = 0.f; }
                else {
                    float diff = isp ? (partdiag - mydiag) : (mydiag - partdiag);
                    float tau = diff / (2.f * across);
                    float tt = (tau >= 0.f ? 1.f : -1.f) / (fabsf(tau) + sqrtf(1.f + tau * tau));
                    cc = rsqrtf(1.f + tt * tt); ss = tt * cc;
                }
                float bme = isp ? -ss : ss;
                float nr[16];
                #pragma unroll
                for (int i = 0; i < 16; i++) {
                    float pv = __shfl_sync(0xffffffffu, a[i], partner);
                    nr[i] = cc * a[i] + bme * pv;
                }
                // column rotation: biV for column i equals bme of lane i
                #pragma unroll
                for (int i = 0; i < 16; i++) {
                    int ui  = (i == 0) ? 15 : (i - 1 - rr + 30) % 15;
                    int pui = (ui == 15) ? 14 : ((ui == 14) ? 15 : 13 - ui);
                    int pi_ = (pui == 15) ? 0 : 1 + ((pui + rr) % 15);
                    float ciV = __shfl_sync(0xffffffffu, cc, i);
                    float biV = __shfl_sync(0xffffffffu, bme, i);
                    a[i] = ciV * nr[i] + biV * nr[pi_];
                }
            }
        }
        float acc = 0.f;
        if (lane < 16) {
            float d = 0.f;
            #pragma unroll
            for (int i = 0; i < 16; i++) if (i == jr) d = a[i];
            float l = logf(fmaxf(d, 1e-30f));
            acc = l * l;
        }
        #pragma unroll
        for (int o = 8; o; o >>= 1) acc += __shfl_xor_sync(0xffffffffu, acc, o);
        dspd = sqrtf(acc);
    } else {
        // =============== warp1: Grassmannian chain (both tables) ===============
        float* xw  = buf1;          // 240 floats
        float* q1w = buf1 + 240;    // 200 floats
        const int tbl = lane / 10;
        const int j = lane - tbl * 10;
        const bool active = lane < 20;

        float Mt[10], Mb[10];
        #pragma unroll
        for (int k = 0; k < 10; k++) { Mt[k] = (k == j && active) ? 1.f : 0.f; Mb[k] = 0.f; }

        #pragma unroll 1
        for (int t = T - 1; t >= 0; t--) {
            int qid = q_ids[b * T + t], aid = a_ids[b * T + t];
            __syncwarp();
            for (int e = lane; e < 100; e += 32) {
                int rr = e / 10, cc = e - rr * 10;
                xw[rr * 12 + cc]       = q_emb_gr[(size_t)qid * 100 + e] * transS[e];
                xw[120 + rr * 12 + cc] = a_emb_gr[(size_t)aid * 100 + e];
            }
            __syncwarp();
            if (active) {
                const float* xb = xw + tbl * 120;
                float u[10], v[10], w1[10], w2[10];
                #pragma unroll
                for (int k = 0; k < 10; k++) { v[k] = 0.f; w2[k] = 0.f; }
                #pragma unroll
                for (int k = 0; k < 10; k++) {
                    float4 r0 = *(const float4*)(xb + k * 12);
                    float4 r1 = *(const float4*)(xb + k * 12 + 4);
                    float4 r2 = *(const float4*)(xb + k * 12 + 8);
                    float xr[10] = {r0.x,r0.y,r0.z,r0.w, r1.x,r1.y,r1.z,r1.w, r2.x,r2.y};
                    float s = 0.f;
                    #pragma unroll
                    for (int c = 0; c < 10; c++) s += xr[c] * Mb[c];
                    u[k] = s;
                    float mtk = Mt[k];
                    #pragma unroll
                    for (int c = 0; c < 10; c++) v[c] += mtk * xr[c];
                }
                #pragma unroll
                for (int k = 0; k < 10; k++) {
                    float4 r0 = *(const float4*)(xb + k * 12);
                    float4 r1 = *(const float4*)(xb + k * 12 + 4);
                    float4 r2 = *(const float4*)(xb + k * 12 + 8);
                    float xr[10] = {r0.x,r0.y,r0.z,r0.w, r1.x,r1.y,r1.z,r1.w, r2.x,r2.y};
                    float s = 0.f;
                    #pragma unroll
                    for (int c = 0; c < 10; c++) s += xr[c] * v[c];
                    w1[k] = s;
                    float uk = u[k];
                    #pragma unroll
                    for (int c = 0; c < 10; c++) w2[c] += uk * xr[c];
                }
                #pragma unroll
                for (int k = 0; k < 10; k++) {
                    Mt[k] = Mt[k] - 2.f * u[k] - 2.f * w1[k];
                    Mb[k] = Mb[k] + 2.f * v[k] - 2.f * w2[k];
                }
            }
        }

        // epilogue: dgr
        if (lane < 10) {
            float Q1[20];
            #pragma unroll
            for (int i = 0; i < 20; i++) Q1[i] = 0.f;
            #pragma unroll
            for (int k = 0; k < 20; k++) {
                float ck = (k < 10) ? Mt[k] : Mb[k - 10];
                const float* yr = YbgT + k * 20;
                float4 y0 = *(const float4*)yr,       y1 = *(const float4*)(yr + 4),
                       y2 = *(const float4*)(yr + 8), y3 = *(const float4*)(yr + 12),
                       y4 = *(const float4*)(yr + 16);
                Q1[0]+=ck*y0.x; Q1[1]+=ck*y0.y; Q1[2]+=ck*y0.z; Q1[3]+=ck*y0.w;
                Q1[4]+=ck*y1.x; Q1[5]+=ck*y1.y; Q1[6]+=ck*y1.z; Q1[7]+=ck*y1.w;
                Q1[8]+=ck*y2.x; Q1[9]+=ck*y2.y; Q1[10]+=ck*y2.z; Q1[11]+=ck*y2.w;
                Q1[12]+=ck*y3.x; Q1[13]+=ck*y3.y; Q1[14]+=ck*y3.z; Q1[15]+=ck*y3.w;
                Q1[16]+=ck*y4.x; Q1[17]+=ck*y4.y; Q1[18]+=ck*y4.z; Q1[19]+=ck*y4.w;
            }
            #pragma unroll
            for (int i = 0; i < 20; i += 4)
                *(float4*)(q1w + j * 20 + i) = make_float4(Q1[i], Q1[i+1], Q1[i+2], Q1[i+3]);
        }
        __syncwarp();
        float s_loc = 0.f;
        if (lane >= 10 && lane < 20) {
            #pragma unroll
            for (int i = 0; i < 10; i++) {
                const float* qc = q1w + i * 20;
                float4 a0 = *(const float4*)qc,       a1 = *(const float4*)(qc + 4),
                       a2 = *(const float4*)(qc + 8), a3 = *(const float4*)(qc + 12),
                       a4 = *(const float4*)(qc + 16);
                float qv[20] = {a0.x,a0.y,a0.z,a0.w, a1.x,a1.y,a1.z,a1.w,
                                a2.x,a2.y,a2.z,a2.w, a3.x,a3.y,a3.z,a3.w,
                                a4.x,a4.y,a4.z,a4.w};
                float d = 0.f;
                #pragma unroll
                for (int k = 0; k < 20; k++) d += qv[k] * ((k < 10) ? Mt[k] : Mb[k - 10]);
                s_loc += d * d;
            }
        }
        #pragma unroll
        for (int o = 16; o; o >>= 1) s_loc += __shfl_xor_sync(0xffffffffu, s_loc, o);
        if (lane == 0) dgr_s = sqrtf(fmaxf(20.f - 2.f * s_loc, 0.f));
    }

    __syncthreads();                                   // dgr_s ready
    if (w == 0 && lane == 0)
        out[b] = -wf[0] * (dspd + dgr_s) + wb[0];
}

// =====================================================================
extern "C" void kernel_launch(void* const* d_in, const int* in_sizes, int n_in,
                              void* d_out, int out_size)
{
    const int*   q_ids      = (const int*)  d_in[0];
    const int*   a_ids      = (const int*)  d_in[1];
    const float* q_emb_spd  = (const float*)d_in[2];
    const float* a_emb_spd  = (const float*)d_in[3];
    const float* ref_params = (const float*)d_in[4];
    const float* bias_spd   = (const float*)d_in[5];
    const float* q_emb_gr   = (const float*)d_in[6];
    const float* a_emb_gr   = (const float*)d_in[7];
    const float* trans_gr   = (const float*)d_in[8];
    const float* bias_gr    = (const float*)d_in[9];
    const float* wf         = (const float*)d_in[10];
    const float* wb         = (const float*)d_in[11];
    float* out = (float*)d_out;

    int B = out_size;
    int T = in_sizes[0] / B;

    precompute_kernel<<<1, 256>>>(ref_params, bias_spd, bias_gr);
    fused_kernel<<<B, 64>>>(q_ids, a_ids, q_emb_spd, a_emb_spd,
                            q_emb_gr, a_emb_gr, trans_gr, wf, wb, out, B, T);
}

// round 16
// speedup vs baseline: 1.1739x; 1.1739x over previous
#include <cuda_runtime.h>
#include <math.h>

#define NS_ITERS 3
#define JAC_SWEEPS 5

// ---------------- device scratch (no allocations allowed) ----------------
__device__ float g_rel[256];            // 16x16 isometry
__device__ float g_W[256];              // expm(-sym(bias_spd)/2)
__device__ float g_Ybg[400];            // cayley(bias_gr) 20x20

// =====================================================================
// warp-level 16x16 helpers. Layout: lane = 2*r + cpar, lane owns row r,
// cols c0..c0+7 (c0 = cpar*8). Smem tiles row-major, stride 20 floats.
// =====================================================================
__device__ __forceinline__ void fullrow16(const float h[8], int cpar, float a[16]) {
    #pragma unroll
    for (int i = 0; i < 8; i++) {
        float o = __shfl_xor_sync(0xffffffffu, h[i], 1);
        a[i]     = cpar ? o    : h[i];
        a[8 + i] = cpar ? h[i] : o;
    }
}

// C(half-row) = a(full row) @ B(smem, stride 20)
__device__ __forceinline__ void wmm16(const float a[16], const float* Bs, int c0, float c[8]) {
    #pragma unroll
    for (int i = 0; i < 8; i++) c[i] = 0.f;
    #pragma unroll
    for (int k = 0; k < 16; k++) {
        float4 b0 = *(const float4*)(Bs + k * 20 + c0);
        float4 b1 = *(const float4*)(Bs + k * 20 + c0 + 4);
        float ak = a[k];
        c[0] += ak * b0.x; c[1] += ak * b0.y; c[2] += ak * b0.z; c[3] += ak * b0.w;
        c[4] += ak * b1.x; c[5] += ak * b1.y; c[6] += ak * b1.z; c[7] += ak * b1.w;
    }
}

// C(half-row) = a(full row) @ B^T (B rows in smem, stride 20)
__device__ __forceinline__ void wmm16t(const float a[16], const float* Bs, int c0, float c[8]) {
    #pragma unroll
    for (int i = 0; i < 8; i++) {
        const float* br = Bs + (c0 + i) * 20;
        float4 b0 = *(const float4*)(br);
        float4 b1 = *(const float4*)(br + 4);
        float4 b2 = *(const float4*)(br + 8);
        float4 b3 = *(const float4*)(br + 12);
        c[i] = a[0]*b0.x + a[1]*b0.y + a[2]*b0.z + a[3]*b0.w
             + a[4]*b1.x + a[5]*b1.y + a[6]*b1.z + a[7]*b1.w
             + a[8]*b2.x + a[9]*b2.y + a[10]*b2.z + a[11]*b2.w
             + a[12]*b3.x + a[13]*b3.y + a[14]*b3.z + a[15]*b3.w;
    }
}

__device__ __forceinline__ void stoh(float* Bs, int r, int c0, const float h[8]) {
    *(float4*)(Bs + r * 20 + c0)     = make_float4(h[0], h[1], h[2], h[3]);
    *(float4*)(Bs + r * 20 + c0 + 4) = make_float4(h[4], h[5], h[6], h[7]);
}

// =====================================================================
// Kernel 0: one-block precompute of batch-invariant matrices (proven)
// =====================================================================
__global__ void precompute_kernel(const float* __restrict__ ref_params,
                                  const float* __restrict__ bias_spd,
                                  const float* __restrict__ bias_gr)
{
    __shared__ float Bs[256], E[256];
    __shared__ float A20[400];
    __shared__ float Aug[20][40];
    __shared__ float prow[40], fcol[20];
    __shared__ float pv;

    const int tid = threadIdx.x;
    const int i = tid >> 4, j = tid & 15;

    // ---- rel = prod of 120 Givens rotations, each lane owns one row ----
    if (tid < 16) {
        float row[16];
        #pragma unroll
        for (int c = 0; c < 16; c++) row[c] = (c == tid) ? 1.f : 0.f;
        int m = 0;
        for (int pi = 0; pi < 16; pi++) {
            for (int pj = pi + 1; pj < 16; pj++) {
                float ang = ref_params[m++];
                float c = cosf(ang), s = sinf(ang);
                float a = row[pi], b = row[pj];
                row[pi] = c * a + s * b;
                row[pj] = -s * a + c * b;
            }
        }
        #pragma unroll
        for (int c = 0; c < 16; c++) g_rel[tid * 16 + c] = row[c];
    }

    // ---- W = expm(-0.25*(bias+bias^T)) via scaling(2^-7) + Taylor-8 ----
    {
        float v = -0.25f * (bias_spd[i * 16 + j] + bias_spd[j * 16 + i]);
        Bs[tid] = v * (1.0f / 128.0f);
        E[tid]  = (i == j) ? 1.f : 0.f;
    }
    __syncthreads();
    for (int k = 8; k >= 1; k--) {
        float a = 0.f;
        #pragma unroll
        for (int kk = 0; kk < 16; kk++) a += Bs[i * 16 + kk] * E[kk * 16 + j];
        __syncthreads();
        E[tid] = ((i == j) ? 1.f : 0.f) + a * (1.0f / (float)k);
        __syncthreads();
    }
    for (int q = 0; q < 7; q++) {
        float a = 0.f;
        #pragma unroll
        for (int kk = 0; kk < 16; kk++) a += E[i * 16 + kk] * E[kk * 16 + j];
        __syncthreads();
        E[tid] = a;
        __syncthreads();
    }
    g_W[tid] = E[tid];

    // ---- Ybg = (I - A)(I + A)^{-1}, A = skew(bias_gr) 20x20 ----
    for (int e = tid; e < 400; e += 256) {
        int ii = e / 20, jj = e % 20;
        float v = 0.f;
        if (ii < 10 && jj >= 10)      v =  bias_gr[ii * 10 + (jj - 10)];
        else if (ii >= 10 && jj < 10) v = -bias_gr[jj * 10 + (ii - 10)];
        A20[e] = v;
    }
    __syncthreads();
    for (int e = tid; e < 800; e += 256) {
        int ii = e / 40, jj = e % 40;
        float v;
        if (jj < 20) v = ((ii == jj) ? 1.f : 0.f) + A20[ii * 20 + jj];
        else         v = ((jj - 20) == ii) ? 1.f : 0.f;
        Aug[ii][jj] = v;
    }
    __syncthreads();
    for (int p = 0; p < 20; p++) {
        if (tid == 0) pv = Aug[p][p];
        __syncthreads();
        if (tid < 40) prow[tid] = Aug[p][tid] / pv;
        if (tid >= 64 && tid < 84) {
            int r = tid - 64;
            fcol[r] = (r == p) ? 0.f : Aug[r][p];
        }
        __syncthreads();
        for (int e = tid; e < 800; e += 256) {
            int ii = e / 40, jj = e % 40;
            Aug[ii][jj] = (ii == p) ? prow[jj] : Aug[ii][jj] - fcol[ii] * prow[jj];
        }
        __syncthreads();
    }
    for (int e = tid; e < 400; e += 256) {
        int ii = e / 20, jj = e % 20;
        float a = 0.f;
        #pragma unroll
        for (int k = 0; k < 20; k++) {
            float l = ((ii == k) ? 1.f : 0.f) - A20[ii * 20 + k];
            a += l * Aug[k][jj + 20];
        }
        g_Ybg[e] = a;
    }
}

// =====================================================================
// Fused kernel: grid = B, block = 64 (2 warps per batch element).
//   warp0: SPD q-chain (P init = Rel)  ->  NS inv-sqrt -> m -> Jacobi -> dspd
//   warp1: SPD a-chain -> Xa to smem  ->  GR chain in QUADS -> dgr
// Both chains use token QUADS with Taylor-2 on the quad sum
// (commutator-only error, measured ~e-6 at output).
// =====================================================================
__global__ void __launch_bounds__(64)
fused_kernel(const int* __restrict__ q_ids, const int* __restrict__ a_ids,
             const float* __restrict__ q_emb_spd, const float* __restrict__ a_emb_spd,
             const float* __restrict__ q_emb_gr, const float* __restrict__ a_emb_gr,
             const float* __restrict__ trans,
             const float* __restrict__ wf, const float* __restrict__ wb,
             float* __restrict__ out, int B, int T)
{
    __shared__ float buf0[640], buf1[640];
    __shared__ float XaS[320];
    __shared__ float RelS[320], WS[320];
    __shared__ float YbgT[400], transS[100];
    __shared__ float dgr_s;

    const int tid = threadIdx.x;
    for (int e = tid; e < 256; e += 64) {
        RelS[(e >> 4) * 20 + (e & 15)] = g_rel[e];
        WS  [(e >> 4) * 20 + (e & 15)] = g_W[e];
    }
    for (int e = tid; e < 400; e += 64) {
        int ii = e / 20, kk = e - ii * 20;
        YbgT[kk * 20 + ii] = g_Ybg[e];
    }
    for (int e = tid; e < 100; e += 64) transS[e] = trans[e];
    __syncthreads();

    const int w = tid >> 5, lane = tid & 31;
    const int b = blockIdx.x;
    const int r = lane >> 1, cpar = lane & 1, c0 = cpar * 8;
    float* bufA = w ? buf1 : buf0;
    float* bufB = bufA + 320;

    // =============== phase 1: SPD chain, table = w ===============
    const int* ids = w ? a_ids : q_ids;
    const float* emb = w ? a_emb_spd : q_emb_spd;

    float P[8];
    if (w == 0) {
        #pragma unroll
        for (int i = 0; i < 8; i++) P[i] = RelS[r * 20 + c0 + i];   // P = Rel
    } else {
        #pragma unroll
        for (int i = 0; i < 8; i++) P[i] = ((r >> 3) == cpar && (r & 7) == i) ? 1.f : 0.f;
    }

    const int nmid = T - 1;
    #pragma unroll 1
    for (int t = 0; t < nmid; t += 4) {
        float er[8] = {0.f,0.f,0.f,0.f,0.f,0.f,0.f,0.f};
        #pragma unroll
        for (int s = 0; s < 4; s++) {
            int tt = t + s;
            if (tt < nmid) {
                int id = ids[b * T + tt];
                const float* rp = emb + (size_t)id * 256 + r * 16 + c0;
                float4 e0 = *(const float4*)rp;
                float4 e1 = *(const float4*)(rp + 4);
                er[0]+=e0.x; er[1]+=e0.y; er[2]+=e0.z; er[3]+=e0.w;
                er[4]+=e1.x; er[5]+=e1.y; er[6]+=e1.z; er[7]+=e1.w;
            }
        }
        __syncwarp();                                  // prior-iter buf reads done
        stoh(bufA, r, c0, er);
        __syncwarp();                                  // Esum visible
        float Ah[8];
        #pragma unroll
        for (int i = 0; i < 8; i++) Ah[i] = 0.25f * (er[i] + bufA[(c0 + i) * 20 + r]);
        stoh(bufB, r, c0, Ah);
        __syncwarp();                                  // S visible
        float a16[16]; fullrow16(Ah, cpar, a16);
        float S2[8];  wmm16(a16, bufB, c0, S2);        // S @ S
        float Sm[8];
        #pragma unroll
        for (int i = 0; i < 8; i++) Sm[i] = Ah[i] + 0.5f * S2[i];
        if ((r >> 3) == cpar) Sm[r & 7] += 1.f;        // I + S + S^2/2
        __syncwarp();                                  // S reads done
        stoh(bufB, r, c0, Sm);
        __syncwarp();                                  // Sm visible
        float p16[16]; fullrow16(P, cpar, p16);
        float PA[8];  wmm16(p16, bufB, c0, PA);        // P @ Sm
        #pragma unroll
        for (int i = 0; i < 8; i++) P[i] = PA[i];
    }

    // last token: Exp = I + A + A^2/2, Y = P @ Exp @ P^T
    float Y[8];
    {
        int id = ids[b * T + (T - 1)];
        const float* rp = emb + (size_t)id * 256 + r * 16 + c0;
        float4 e0 = *(const float4*)rp;
        float4 e1 = *(const float4*)(rp + 4);
        __syncwarp();
        *(float4*)(bufA + r * 20 + c0)     = e0;
        *(float4*)(bufA + r * 20 + c0 + 4) = e1;
        __syncwarp();
        float el[8] = {e0.x, e0.y, e0.z, e0.w, e1.x, e1.y, e1.z, e1.w};
        float Ah[8];
        #pragma unroll
        for (int i = 0; i < 8; i++) Ah[i] = 0.5f * (el[i] + bufA[(c0 + i) * 20 + r]);
        stoh(bufB, r, c0, Ah);
        __syncwarp();
        float a16[16]; fullrow16(Ah, cpar, a16);
        float A2[8];  wmm16(a16, bufB, c0, A2);
        float Sm[8];
        #pragma unroll
        for (int i = 0; i < 8; i++) Sm[i] = Ah[i] + 0.5f * A2[i];
        if ((r >> 3) == cpar) Sm[r & 7] += 1.f;
        __syncwarp();
        stoh(bufB, r, c0, Sm);
        stoh(bufA, r, c0, P);                          // stash P for transpose
        __syncwarp();
        float p16[16]; fullrow16(P, cpar, p16);
        float Pn[8];  wmm16(p16, bufB, c0, Pn);        // P @ Exp
        float t16[16]; fullrow16(Pn, cpar, t16);
        wmm16t(t16, bufA, c0, Y);                      // @ P^T
    }
    if (w == 1) stoh(XaS, r, c0, Y);                   // publish Xa
    __syncthreads();                                   // ---- phase boundary ----

    // =============== phase 2 ===============
    float dspd = 0.f;
    if (w == 0) {
        // ---- Newton-Schulz: Z -> X^{-1/2}  (X = Y, already rel-conjugated) ----
        float Z[8];
        #pragma unroll
        for (int i = 0; i < 8; i++) Z[i] = ((r >> 3) == cpar && (r & 7) == i) ? 1.f : 0.f;
        #pragma unroll 1
        for (int it = 0; it < NS_ITERS; it++) {
            __syncwarp(); stoh(bufA, r, c0, Y); __syncwarp();
            float z16[16]; fullrow16(Z, cpar, z16);
            float G[8];   wmm16(z16, bufA, c0, G);      // Z@Y
            #pragma unroll
            for (int i = 0; i < 8; i++) G[i] = -0.5f * G[i];
            if ((r >> 3) == cpar) G[r & 7] += 1.5f;
            __syncwarp(); stoh(bufB, r, c0, G); __syncwarp();
            float y16[16]; fullrow16(Y, cpar, y16);
            float Yn[8];  wmm16(y16, bufB, c0, Yn);     // Y@G
            __syncwarp(); stoh(bufA, r, c0, Z); __syncwarp();
            float g16[16]; fullrow16(G, cpar, g16);
            float Zn[8];  wmm16(g16, bufA, c0, Zn);     // G@Z
            #pragma unroll
            for (int i = 0; i < 8; i++) { Y[i] = Yn[i]; Z[i] = Zn[i]; }
        }

        // ---- m = C @ Xa @ C^T, C = W@Z (W,Z symmetric) ----
        __syncwarp(); stoh(bufA, r, c0, Z); __syncwarp();
        {
            const float* wr = WS + r * 20;
            float4 w0 = *(const float4*)wr,       w1 = *(const float4*)(wr + 4),
                   w2 = *(const float4*)(wr + 8), w3 = *(const float4*)(wr + 12);
            float wrow[16] = {w0.x,w0.y,w0.z,w0.w, w1.x,w1.y,w1.z,w1.w,
                              w2.x,w2.y,w2.z,w2.w, w3.x,w3.y,w3.z,w3.w};
            float Ch[8]; wmm16(wrow, bufA, c0, Ch);     // C = W@Z
            __syncwarp(); stoh(bufB, r, c0, Ch); __syncwarp();
            float c16[16]; fullrow16(Ch, cpar, c16);
            float T1[8]; wmm16(c16, XaS, c0, T1);       // C@Xa
            float t16[16]; fullrow16(T1, cpar, t16);
            float Mh[8]; wmm16t(t16, bufB, c0, Mh);     // @C^T
            __syncwarp(); stoh(bufA, r, c0, Mh); __syncwarp();
        }

        // ---- shfl-resident Jacobi (rows in registers) ----
        const int jr = lane & 15;
        float a[16];
        {
            const float* rp = bufA + jr * 20;
            float4 v0 = *(const float4*)rp,        v1 = *(const float4*)(rp + 4),
                   v2 = *(const float4*)(rp + 8),  v3 = *(const float4*)(rp + 12);
            a[0]=v0.x; a[1]=v0.y; a[2]=v0.z; a[3]=v0.w;
            a[4]=v1.x; a[5]=v1.y; a[6]=v1.z; a[7]=v1.w;
            a[8]=v2.x; a[9]=v2.y; a[10]=v2.z; a[11]=v2.w;
            a[12]=v3.x; a[13]=v3.y; a[14]=v3.z; a[15]=v3.w;
        }
        #pragma unroll 1
        for (int sweep = 0; sweep < JAC_SWEEPS; sweep++) {
            #pragma unroll
            for (int rr = 0; rr < 15; rr++) {
                int u  = (jr == 0) ? 15 : (jr - 1 - rr + 30) % 15;
                int pu = (u == 15) ? 14 : ((u == 14) ? 15 : 13 - u);
                int partner = (pu == 15) ? 0 : 1 + ((pu + rr) % 15);
                bool isp = (jr == 0) || (u <= 6);
                float mydiag = 0.f, across = 0.f;
                #pragma unroll
                for (int i = 0; i < 16; i++) {
                    if (i == jr)      mydiag = a[i];
                    if (i == partner) across = a[i];
                }
                float partdiag = __shfl_sync(0xffffffffu, mydiag, partner);
                float cc, ss;
                if (fabsf(across) < 1e-30f) { cc = 1.f; ss = 0.f; }
                else {
                    float diff = isp ? (partdiag - mydiag) : (mydiag - partdiag);
                    float tau = diff / (2.f * across);
                    float tt = (tau >= 0.f ? 1.f : -1.f) / (fabsf(tau) + sqrtf(1.f + tau * tau));
                    cc = rsqrtf(1.f + tt * tt); ss = tt * cc;
                }
                float bme = isp ? -ss : ss;
                float nr[16];
                #pragma unroll
                for (int i = 0; i < 16; i++) {
                    float pv = __shfl_sync(0xffffffffu, a[i], partner);
                    nr[i] = cc * a[i] + bme * pv;
                }
                // column rotation: biV for column i equals bme of lane i
                #pragma unroll
                for (int i = 0; i < 16; i++) {
                    int ui  = (i == 0) ? 15 : (i - 1 - rr + 30) % 15;
                    int pui = (ui == 15) ? 14 : ((ui == 14) ? 15 : 13 - ui);
                    int pi_ = (pui == 15) ? 0 : 1 + ((pui + rr) % 15);
                    float ciV = __shfl_sync(0xffffffffu, cc, i);
                    float biV = __shfl_sync(0xffffffffu, bme, i);
                    a[i] = ciV * nr[i] + biV * nr[pi_];
                }
            }
        }
        float acc = 0.f;
        if (lane < 16) {
            float d = 0.f;
            #pragma unroll
            for (int i = 0; i < 16; i++) if (i == jr) d = a[i];
            float l = logf(fmaxf(d, 1e-30f));
            acc = l * l;
        }
        #pragma unroll
        for (int o = 8; o; o >>= 1) acc += __shfl_xor_sync(0xffffffffu, acc, o);
        dspd = sqrtf(acc);
    } else {
        // =============== warp1: Grassmannian chain in QUADS ===============
        float* xw  = buf1;          // 240 floats
        float* q1w = buf1 + 240;    // 200 floats
        const int tbl = lane / 10;
        const int j = lane - tbl * 10;
        const bool active = lane < 20;

        float Mt[10], Mb[10];
        #pragma unroll
        for (int k = 0; k < 10; k++) { Mt[k] = (k == j && active) ? 1.f : 0.f; Mb[k] = 0.f; }

        // process tokens back-to-front in groups of 4; factor = I - 2S + 2S^2,
        // S = sum of the 4 token tangents (linear in x -> same update code).
        #pragma unroll 1
        for (int t = T - 4; t > -4; t -= 4) {
            int qid[4], aid[4];
            #pragma unroll
            for (int s = 0; s < 4; s++) {
                int tt = t + s;
                qid[s] = (tt >= 0) ? q_ids[b * T + tt] : -1;
                aid[s] = (tt >= 0) ? a_ids[b * T + tt] : -1;
            }
            __syncwarp();                              // prior compute reads done
            for (int e = lane; e < 100; e += 32) {
                float sq = 0.f, sa = 0.f;
                #pragma unroll
                for (int s = 0; s < 4; s++) {
                    if (qid[s] >= 0) {
                        sq += q_emb_gr[(size_t)qid[s] * 100 + e];
                        sa += a_emb_gr[(size_t)aid[s] * 100 + e];
                    }
                }
                int rr = e / 10, cc = e - rr * 10;
                xw[rr * 12 + cc]       = sq * transS[e];
                xw[120 + rr * 12 + cc] = sa;
            }
            __syncwarp();                              // x (=S blocks) visible
            if (active) {
                const float* xb = xw + tbl * 120;
                float u[10], v[10], w1[10], w2[10];
                #pragma unroll
                for (int k = 0; k < 10; k++) { v[k] = 0.f; w2[k] = 0.f; }
                #pragma unroll
                for (int k = 0; k < 10; k++) {
                    float4 r0 = *(const float4*)(xb + k * 12);
                    float4 r1 = *(const float4*)(xb + k * 12 + 4);
                    float4 r2 = *(const float4*)(xb + k * 12 + 8);
                    float xr[10] = {r0.x,r0.y,r0.z,r0.w, r1.x,r1.y,r1.z,r1.w, r2.x,r2.y};
                    float s = 0.f;
                    #pragma unroll
                    for (int c = 0; c < 10; c++) s += xr[c] * Mb[c];
                    u[k] = s;
                    float mtk = Mt[k];
                    #pragma unroll
                    for (int c = 0; c < 10; c++) v[c] += mtk * xr[c];
                }
                #pragma unroll
                for (int k = 0; k < 10; k++) {
                    float4 r0 = *(const float4*)(xb + k * 12);
                    float4 r1 = *(const float4*)(xb + k * 12 + 4);
                    float4 r2 = *(const float4*)(xb + k * 12 + 8);
                    float xr[10] = {r0.x,r0.y,r0.z,r0.w, r1.x,r1.y,r1.z,r1.w, r2.x,r2.y};
                    float s = 0.f;
                    #pragma unroll
                    for (int c = 0; c < 10; c++) s += xr[c] * v[c];
                    w1[k] = s;
                    float uk = u[k];
                    #pragma unroll
                    for (int c = 0; c < 10; c++) w2[c] += uk * xr[c];
                }
                #pragma unroll
                for (int k = 0; k < 10; k++) {
                    Mt[k] = Mt[k] - 2.f * u[k] - 2.f * w1[k];
                    Mb[k] = Mb[k] + 2.f * v[k] - 2.f * w2[k];
                }
            }
        }

        // epilogue: dgr
        if (lane < 10) {
            float Q1[20];
            #pragma unroll
            for (int i = 0; i < 20; i++) Q1[i] = 0.f;
            #pragma unroll
            for (int k = 0; k < 20; k++) {
                float ck = (k < 10) ? Mt[k] : Mb[k - 10];
                const float* yr = YbgT + k * 20;
                float4 y0 = *(const float4*)yr,       y1 = *(const float4*)(yr + 4),
                       y2 = *(const float4*)(yr + 8), y3 = *(const float4*)(yr + 12),
                       y4 = *(const float4*)(yr + 16);
                Q1[0]+=ck*y0.x; Q1[1]+=ck*y0.y; Q1[2]+=ck*y0.z; Q1[3]+=ck*y0.w;
                Q1[4]+=ck*y1.x; Q1[5]+=ck*y1.y; Q1[6]+=ck*y1.z; Q1[7]+=ck*y1.w;
                Q1[8]+=ck*y2.x; Q1[9]+=ck*y2.y; Q1[10]+=ck*y2.z; Q1[11]+=ck*y2.w;
                Q1[12]+=ck*y3.x; Q1[13]+=ck*y3.y; Q1[14]+=ck*y3.z; Q1[15]+=ck*y3.w;
                Q1[16]+=ck*y4.x; Q1[17]+=ck*y4.y; Q1[18]+=ck*y4.z; Q1[19]+=ck*y4.w;
            }
            #pragma unroll
            for (int i = 0; i < 20; i += 4)
                *(float4*)(q1w + j * 20 + i) = make_float4(Q1[i], Q1[i+1], Q1[i+2], Q1[i+3]);
        }
        __syncwarp();
        float s_loc = 0.f;
        if (lane >= 10 && lane < 20) {
            #pragma unroll
            for (int i = 0; i < 10; i++) {
                const float* qc = q1w + i * 20;
                float4 a0 = *(const float4*)qc,       a1 = *(const float4*)(qc + 4),
                       a2 = *(const float4*)(qc + 8), a3 = *(const float4*)(qc + 12),
                       a4 = *(const float4*)(qc + 16);
                float qv[20] = {a0.x,a0.y,a0.z,a0.w, a1.x,a1.y,a1.z,a1.w,
                                a2.x,a2.y,a2.z,a2.w, a3.x,a3.y,a3.z,a3.w,
                                a4.x,a4.y,a4.z,a4.w};
                float d = 0.f;
                #pragma unroll
                for (int k = 0; k < 20; k++) d += qv[k] * ((k < 10) ? Mt[k] : Mb[k - 10]);
                s_loc += d * d;
            }
        }
        #pragma unroll
        for (int o = 16; o; o >>= 1) s_loc += __shfl_xor_sync(0xffffffffu, s_loc, o);
        if (lane == 0) dgr_s = sqrtf(fmaxf(20.f - 2.f * s_loc, 0.f));
    }

    __syncthreads();                                   // dgr_s ready
    if (w == 0 && lane == 0)
        out[b] = -wf[0] * (dspd + dgr_s) + wb[0];
}

// =====================================================================
extern "C" void kernel_launch(void* const* d_in, const int* in_sizes, int n_in,
                              void* d_out, int out_size)
{
    const int*   q_ids      = (const int*)  d_in[0];
    const int*   a_ids      = (const int*)  d_in[1];
    const float* q_emb_spd  = (const float*)d_in[2];
    const float* a_emb_spd  = (const float*)d_in[3];
    const float* ref_params = (const float*)d_in[4];
    const float* bias_spd   = (const float*)d_in[5];
    const float* q_emb_gr   = (const float*)d_in[6];
    const float* a_emb_gr   = (const float*)d_in[7];
    const float* trans_gr   = (const float*)d_in[8];
    const float* bias_gr    = (const float*)d_in[9];
    const float* wf         = (const float*)d_in[10];
    const float* wb         = (const float*)d_in[11];
    float* out = (float*)d_out;

    int B = out_size;
    int T = in_sizes[0] / B;

    precompute_kernel<<<1, 256>>>(ref_params, bias_spd, bias_gr);
    fused_kernel<<<B, 64>>>(q_ids, a_ids, q_emb_spd, a_emb_spd,
                            q_emb_gr, a_emb_gr, trans_gr, wf, wb, out, B, T);
}

// round 17
// speedup vs baseline: 1.3214x; 1.1256x over previous
#include <cuda_runtime.h>
#include <math.h>

#define NS_ITERS 3
#define JAC_SWEEPS 5

// ---------------- device scratch (no allocations allowed) ----------------
__device__ float g_rel[256];            // 16x16 isometry
__device__ float g_W[256];              // expm(-sym(bias_spd)/2)
__device__ float g_Ybg[400];            // cayley(bias_gr) 20x20

// =====================================================================
// warp-level 16x16 helpers. Layout: lane = 2*r + cpar, lane owns row r,
// cols c0..c0+7 (c0 = cpar*8). Smem tiles row-major, stride 20 floats.
// =====================================================================
__device__ __forceinline__ void fullrow16(const float h[8], int cpar, float a[16]) {
    #pragma unroll
    for (int i = 0; i < 8; i++) {
        float o = __shfl_xor_sync(0xffffffffu, h[i], 1);
        a[i]     = cpar ? o    : h[i];
        a[8 + i] = cpar ? h[i] : o;
    }
}

// C(half-row) = a(full row) @ B(smem, stride 20)
__device__ __forceinline__ void wmm16(const float a[16], const float* Bs, int c0, float c[8]) {
    #pragma unroll
    for (int i = 0; i < 8; i++) c[i] = 0.f;
    #pragma unroll
    for (int k = 0; k < 16; k++) {
        float4 b0 = *(const float4*)(Bs + k * 20 + c0);
        float4 b1 = *(const float4*)(Bs + k * 20 + c0 + 4);
        float ak = a[k];
        c[0] += ak * b0.x; c[1] += ak * b0.y; c[2] += ak * b0.z; c[3] += ak * b0.w;
        c[4] += ak * b1.x; c[5] += ak * b1.y; c[6] += ak * b1.z; c[7] += ak * b1.w;
    }
}

// C(half-row) = a(full row) @ B^T (B rows in smem, stride 20)
__device__ __forceinline__ void wmm16t(const float a[16], const float* Bs, int c0, float c[8]) {
    #pragma unroll
    for (int i = 0; i < 8; i++) {
        const float* br = Bs + (c0 + i) * 20;
        float4 b0 = *(const float4*)(br);
        float4 b1 = *(const float4*)(br + 4);
        float4 b2 = *(const float4*)(br + 8);
        float4 b3 = *(const float4*)(br + 12);
        c[i] = a[0]*b0.x + a[1]*b0.y + a[2]*b0.z + a[3]*b0.w
             + a[4]*b1.x + a[5]*b1.y + a[6]*b1.z + a[7]*b1.w
             + a[8]*b2.x + a[9]*b2.y + a[10]*b2.z + a[11]*b2.w
             + a[12]*b3.x + a[13]*b3.y + a[14]*b3.z + a[15]*b3.w;
    }
}

__device__ __forceinline__ void stoh(float* Bs, int r, int c0, const float h[8]) {
    *(float4*)(Bs + r * 20 + c0)     = make_float4(h[0], h[1], h[2], h[3]);
    *(float4*)(Bs + r * 20 + c0 + 4) = make_float4(h[4], h[5], h[6], h[7]);
}

// =====================================================================
// Kernel 0: one-block precompute of batch-invariant matrices (proven)
// =====================================================================
__global__ void precompute_kernel(const float* __restrict__ ref_params,
                                  const float* __restrict__ bias_spd,
                                  const float* __restrict__ bias_gr)
{
    __shared__ float Bs[256], E[256];
    __shared__ float A20[400];
    __shared__ float Aug[20][40];
    __shared__ float prow[40], fcol[20];
    __shared__ float pv;

    const int tid = threadIdx.x;
    const int i = tid >> 4, j = tid & 15;

    // ---- rel = prod of 120 Givens rotations, each lane owns one row ----
    if (tid < 16) {
        float row[16];
        #pragma unroll
        for (int c = 0; c < 16; c++) row[c] = (c == tid) ? 1.f : 0.f;
        int m = 0;
        for (int pi = 0; pi < 16; pi++) {
            for (int pj = pi + 1; pj < 16; pj++) {
                float ang = ref_params[m++];
                float c = cosf(ang), s = sinf(ang);
                float a = row[pi], b = row[pj];
                row[pi] = c * a + s * b;
                row[pj] = -s * a + c * b;
            }
        }
        #pragma unroll
        for (int c = 0; c < 16; c++) g_rel[tid * 16 + c] = row[c];
    }

    // ---- W = expm(-0.25*(bias+bias^T)) via scaling(2^-7) + Taylor-8 ----
    {
        float v = -0.25f * (bias_spd[i * 16 + j] + bias_spd[j * 16 + i]);
        Bs[tid] = v * (1.0f / 128.0f);
        E[tid]  = (i == j) ? 1.f : 0.f;
    }
    __syncthreads();
    for (int k = 8; k >= 1; k--) {
        float a = 0.f;
        #pragma unroll
        for (int kk = 0; kk < 16; kk++) a += Bs[i * 16 + kk] * E[kk * 16 + j];
        __syncthreads();
        E[tid] = ((i == j) ? 1.f : 0.f) + a * (1.0f / (float)k);
        __syncthreads();
    }
    for (int q = 0; q < 7; q++) {
        float a = 0.f;
        #pragma unroll
        for (int kk = 0; kk < 16; kk++) a += E[i * 16 + kk] * E[kk * 16 + j];
        __syncthreads();
        E[tid] = a;
        __syncthreads();
    }
    g_W[tid] = E[tid];

    // ---- Ybg = (I - A)(I + A)^{-1}, A = skew(bias_gr) 20x20 ----
    for (int e = tid; e < 400; e += 256) {
        int ii = e / 20, jj = e % 20;
        float v = 0.f;
        if (ii < 10 && jj >= 10)      v =  bias_gr[ii * 10 + (jj - 10)];
        else if (ii >= 10 && jj < 10) v = -bias_gr[jj * 10 + (ii - 10)];
        A20[e] = v;
    }
    __syncthreads();
    for (int e = tid; e < 800; e += 256) {
        int ii = e / 40, jj = e % 40;
        float v;
        if (jj < 20) v = ((ii == jj) ? 1.f : 0.f) + A20[ii * 20 + jj];
        else         v = ((jj - 20) == ii) ? 1.f : 0.f;
        Aug[ii][jj] = v;
    }
    __syncthreads();
    for (int p = 0; p < 20; p++) {
        if (tid == 0) pv = Aug[p][p];
        __syncthreads();
        if (tid < 40) prow[tid] = Aug[p][tid] / pv;
        if (tid >= 64 && tid < 84) {
            int r = tid - 64;
            fcol[r] = (r == p) ? 0.f : Aug[r][p];
        }
        __syncthreads();
        for (int e = tid; e < 800; e += 256) {
            int ii = e / 40, jj = e % 40;
            Aug[ii][jj] = (ii == p) ? prow[jj] : Aug[ii][jj] - fcol[ii] * prow[jj];
        }
        __syncthreads();
    }
    for (int e = tid; e < 400; e += 256) {
        int ii = e / 20, jj = e % 20;
        float a = 0.f;
        #pragma unroll
        for (int k = 0; k < 20; k++) {
            float l = ((ii == k) ? 1.f : 0.f) - A20[ii * 20 + k];
            a += l * Aug[k][jj + 20];
        }
        g_Ybg[e] = a;
    }
}

// =====================================================================
// Fused kernel: grid = B, block = 64 (2 warps per batch element).
//   warp0: SPD q-chain (P init = Rel) -> NS inv-sqrt -> m -> Jacobi -> dspd
//   warp1: SPD a-chain -> Xa to smem -> GR chain in QUADS -> dgr
// =====================================================================
__global__ void __launch_bounds__(64)
fused_kernel(const int* __restrict__ q_ids, const int* __restrict__ a_ids,
             const float* __restrict__ q_emb_spd, const float* __restrict__ a_emb_spd,
             const float* __restrict__ q_emb_gr, const float* __restrict__ a_emb_gr,
             const float* __restrict__ trans,
             const float* __restrict__ wf, const float* __restrict__ wb,
             float* __restrict__ out, int B, int T)
{
    __shared__ float buf0[640], buf1[640];
    __shared__ float XaS[320];
    __shared__ float RelS[320], WS[320];
    __shared__ float YbgT[400], transS[100];
    __shared__ float dgr_s;

    const int tid = threadIdx.x;
    for (int e = tid; e < 256; e += 64) {
        RelS[(e >> 4) * 20 + (e & 15)] = g_rel[e];
        WS  [(e >> 4) * 20 + (e & 15)] = g_W[e];
    }
    for (int e = tid; e < 400; e += 64) {
        int ii = e / 20, kk = e - ii * 20;
        YbgT[kk * 20 + ii] = g_Ybg[e];
    }
    for (int e = tid; e < 100; e += 64) transS[e] = trans[e];
    __syncthreads();

    const int w = tid >> 5, lane = tid & 31;
    const int b = blockIdx.x;
    const int r = lane >> 1, cpar = lane & 1, c0 = cpar * 8;
    float* bufA = w ? buf1 : buf0;
    float* bufB = bufA + 320;

    // =============== phase 1: SPD chain, table = w ===============
    const int* ids = w ? a_ids : q_ids;
    const float* emb = w ? a_emb_spd : q_emb_spd;

    float P[8];
    if (w == 0) {
        #pragma unroll
        for (int i = 0; i < 8; i++) P[i] = RelS[r * 20 + c0 + i];   // P = Rel
    } else {
        #pragma unroll
        for (int i = 0; i < 8; i++) P[i] = ((r >> 3) == cpar && (r & 7) == i) ? 1.f : 0.f;
    }

    const int nmid = T - 1;
    #pragma unroll 1
    for (int t = 0; t < nmid; t += 4) {
        float er[8] = {0.f,0.f,0.f,0.f,0.f,0.f,0.f,0.f};
        #pragma unroll
        for (int s = 0; s < 4; s++) {
            int tt = t + s;
            if (tt < nmid) {
                int id = ids[b * T + tt];
                const float* rp = emb + (size_t)id * 256 + r * 16 + c0;
                float4 e0 = *(const float4*)rp;
                float4 e1 = *(const float4*)(rp + 4);
                er[0]+=e0.x; er[1]+=e0.y; er[2]+=e0.z; er[3]+=e0.w;
                er[4]+=e1.x; er[5]+=e1.y; er[6]+=e1.z; er[7]+=e1.w;
            }
        }
        __syncwarp();                                  // prior-iter buf reads done
        stoh(bufA, r, c0, er);
        __syncwarp();                                  // Esum visible
        float Ah[8];
        #pragma unroll
        for (int i = 0; i < 8; i++) Ah[i] = 0.25f * (er[i] + bufA[(c0 + i) * 20 + r]);
        stoh(bufB, r, c0, Ah);
        __syncwarp();                                  // S visible
        float a16[16]; fullrow16(Ah, cpar, a16);
        float S2[8];  wmm16(a16, bufB, c0, S2);        // S @ S
        float Sm[8];
        #pragma unroll
        for (int i = 0; i < 8; i++) Sm[i] = Ah[i] + 0.5f * S2[i];
        if ((r >> 3) == cpar) Sm[r & 7] += 1.f;        // I + S + S^2/2
        __syncwarp();                                  // S reads done
        stoh(bufB, r, c0, Sm);
        __syncwarp();                                  // Sm visible
        float p16[16]; fullrow16(P, cpar, p16);
        float PA[8];  wmm16(p16, bufB, c0, PA);        // P @ Sm
        #pragma unroll
        for (int i = 0; i < 8; i++) P[i] = PA[i];
    }

    // last token: Exp = I + A + A^2/2, Y = P @ Exp @ P^T
    float Y[8];
    {
        int id = ids[b * T + (T - 1)];
        const float* rp = emb + (size_t)id * 256 + r * 16 + c0;
        float4 e0 = *(const float4*)rp;
        float4 e1 = *(const float4*)(rp + 4);
        __syncwarp();
        *(float4*)(bufA + r * 20 + c0)     = e0;
        *(float4*)(bufA + r * 20 + c0 + 4) = e1;
        __syncwarp();
        float el[8] = {e0.x, e0.y, e0.z, e0.w, e1.x, e1.y, e1.z, e1.w};
        float Ah[8];
        #pragma unroll
        for (int i = 0; i < 8; i++) Ah[i] = 0.5f * (el[i] + bufA[(c0 + i) * 20 + r]);
        stoh(bufB, r, c0, Ah);
        __syncwarp();
        float a16[16]; fullrow16(Ah, cpar, a16);
        float A2[8];  wmm16(a16, bufB, c0, A2);
        float Sm[8];
        #pragma unroll
        for (int i = 0; i < 8; i++) Sm[i] = Ah[i] + 0.5f * A2[i];
        if ((r >> 3) == cpar) Sm[r & 7] += 1.f;
        __syncwarp();
        stoh(bufB, r, c0, Sm);
        stoh(bufA, r, c0, P);                          // stash P for transpose
        __syncwarp();
        float p16[16]; fullrow16(P, cpar, p16);
        float Pn[8];  wmm16(p16, bufB, c0, Pn);        // P @ Exp
        float t16[16]; fullrow16(Pn, cpar, t16);
        wmm16t(t16, bufA, c0, Y);                      // @ P^T
    }
    if (w == 1) stoh(XaS, r, c0, Y);                   // publish Xa
    __syncthreads();                                   // ---- phase boundary ----

    // =============== phase 2 ===============
    float dspd = 0.f;
    if (w == 0) {
        // ---- Newton-Schulz: Z -> X^{-1/2} ----
        float Z[8];
        // iter 0 specialized (Z = I): G = 1.5I - 0.5Y; Y1 = 1.5Y - 0.5Y^2; Z1 = G
        {
            __syncwarp(); stoh(bufA, r, c0, Y); __syncwarp();
            float y16[16]; fullrow16(Y, cpar, y16);
            float Y2[8]; wmm16(y16, bufA, c0, Y2);     // Y@Y
            #pragma unroll
            for (int i = 0; i < 8; i++) {
                Z[i] = -0.5f * Y[i];
                Y[i] = 1.5f * Y[i] - 0.5f * Y2[i];
            }
            if ((r >> 3) == cpar) Z[r & 7] += 1.5f;
        }
        #pragma unroll 1
        for (int it = 1; it < NS_ITERS; it++) {
            __syncwarp(); stoh(bufA, r, c0, Y); __syncwarp();
            float z16[16]; fullrow16(Z, cpar, z16);
            float G[8];   wmm16(z16, bufA, c0, G);      // Z@Y
            #pragma unroll
            for (int i = 0; i < 8; i++) G[i] = -0.5f * G[i];
            if ((r >> 3) == cpar) G[r & 7] += 1.5f;
            __syncwarp(); stoh(bufB, r, c0, G); __syncwarp();
            float y16[16]; fullrow16(Y, cpar, y16);
            float Yn[8];  wmm16(y16, bufB, c0, Yn);     // Y@G
            __syncwarp(); stoh(bufA, r, c0, Z); __syncwarp();
            float g16[16]; fullrow16(G, cpar, g16);
            float Zn[8];  wmm16(g16, bufA, c0, Zn);     // G@Z
            #pragma unroll
            for (int i = 0; i < 8; i++) { Y[i] = Yn[i]; Z[i] = Zn[i]; }
        }

        // ---- m = C @ Xa @ C^T, C = W@Z (W,Z symmetric) ----
        __syncwarp(); stoh(bufA, r, c0, Z); __syncwarp();
        {
            const float* wr = WS + r * 20;
            float4 w0 = *(const float4*)wr,       w1 = *(const float4*)(wr + 4),
                   w2 = *(const float4*)(wr + 8), w3 = *(const float4*)(wr + 12);
            float wrow[16] = {w0.x,w0.y,w0.z,w0.w, w1.x,w1.y,w1.z,w1.w,
                              w2.x,w2.y,w2.z,w2.w, w3.x,w3.y,w3.z,w3.w};
            float Ch[8]; wmm16(wrow, bufA, c0, Ch);     // C = W@Z
            __syncwarp(); stoh(bufB, r, c0, Ch); __syncwarp();
            float c16[16]; fullrow16(Ch, cpar, c16);
            float T1[8]; wmm16(c16, XaS, c0, T1);       // C@Xa
            float t16[16]; fullrow16(T1, cpar, t16);
            float Mh[8]; wmm16t(t16, bufB, c0, Mh);     // @C^T
            __syncwarp(); stoh(bufA, r, c0, Mh); __syncwarp();
        }

        // ---- shfl-resident Jacobi with incremental diagonal and
        //      smem-broadcast column coefficients ----
        const int jr = lane & 15;
        float a[16];
        {
            const float* rp = bufA + jr * 20;
            float4 v0 = *(const float4*)rp,        v1 = *(const float4*)(rp + 4),
                   v2 = *(const float4*)(rp + 8),  v3 = *(const float4*)(rp + 12);
            a[0]=v0.x; a[1]=v0.y; a[2]=v0.z; a[3]=v0.w;
            a[4]=v1.x; a[5]=v1.y; a[6]=v1.z; a[7]=v1.w;
            a[8]=v2.x; a[9]=v2.y; a[10]=v2.z; a[11]=v2.w;
            a[12]=v3.x; a[13]=v3.y; a[14]=v3.z; a[15]=v3.w;
        }
        float mydiag = 0.f;
        #pragma unroll
        for (int i = 0; i < 16; i++) if (i == jr) mydiag = a[i];
        float* ccS = bufB;          // [16]
        float* bbS = bufB + 16;     // [16]
        __syncwarp();
        #pragma unroll 1
        for (int sweep = 0; sweep < JAC_SWEEPS; sweep++) {
            #pragma unroll
            for (int rr = 0; rr < 15; rr++) {
                int u  = (jr == 0) ? 15 : (jr - 1 - rr + 30) % 15;
                int pu = (u == 15) ? 14 : ((u == 14) ? 15 : 13 - u);
                int partner = (pu == 15) ? 0 : 1 + ((pu + rr) % 15);
                bool isp = (jr == 0) || (u <= 6);
                float across = 0.f;
                #pragma unroll
                for (int i = 0; i < 16; i++) if (i == partner) across = a[i];
                float partdiag = __shfl_sync(0xffffffffu, mydiag, partner);
                float cc = 1.f, tt = 0.f, bme = 0.f;
                if (fabsf(across) >= 1e-30f) {
                    float diff = isp ? (partdiag - mydiag) : (mydiag - partdiag);
                    float tau = diff / (2.f * across);
                    tt = (tau >= 0.f ? 1.f : -1.f) / (fabsf(tau) + sqrtf(1.f + tau * tau));
                    cc = rsqrtf(1.f + tt * tt);
                    float ss = tt * cc;
                    bme = isp ? -ss : ss;
                }
                if (lane < 16) { ccS[jr] = cc; bbS[jr] = bme; }
                __syncwarp();                          // coeffs visible
                // row rotation
                float nr[16];
                #pragma unroll
                for (int i = 0; i < 16; i++) {
                    float pv = __shfl_sync(0xffffffffu, a[i], partner);
                    nr[i] = cc * a[i] + bme * pv;
                }
                // column rotation: coefficients from smem broadcast, 4 at a time
                #pragma unroll
                for (int ch = 0; ch < 4; ch++) {
                    float4 cv = *(const float4*)(ccS + ch * 4);
                    float4 bv = *(const float4*)(bbS + ch * 4);
                    float cA[4] = {cv.x, cv.y, cv.z, cv.w};
                    float bA[4] = {bv.x, bv.y, bv.z, bv.w};
                    #pragma unroll
                    for (int q = 0; q < 4; q++) {
                        const int i = ch * 4 + q;
                        int ui  = (i == 0) ? 15 : (i - 1 - rr + 30) % 15;
                        int pui = (ui == 15) ? 14 : ((ui == 14) ? 15 : 13 - ui);
                        int pi_ = (pui == 15) ? 0 : 1 + ((pui + rr) % 15);
                        a[i] = cA[q] * nr[i] + bA[q] * nr[pi_];
                    }
                }
                // incremental diagonal: a'_pp = a_pp - t*a_pq ; a'_qq = a_qq + t*a_pq
                mydiag = fmaf(isp ? -tt : tt, across, mydiag);
                __syncwarp();                          // coeff reads done
            }
        }
        float acc = 0.f;
        if (lane < 16) {
            float l = logf(fmaxf(mydiag, 1e-30f));
            acc = l * l;
        }
        #pragma unroll
        for (int o = 8; o; o >>= 1) acc += __shfl_xor_sync(0xffffffffu, acc, o);
        dspd = sqrtf(acc);
    } else {
        // =============== warp1: Grassmannian chain in QUADS ===============
        float* xw  = buf1;          // 240 floats
        float* q1w = buf1 + 240;    // 200 floats
        const int tbl = lane / 10;
        const int j = lane - tbl * 10;
        const bool active = lane < 20;

        float Mt[10], Mb[10];
        #pragma unroll
        for (int k = 0; k < 10; k++) { Mt[k] = (k == j && active) ? 1.f : 0.f; Mb[k] = 0.f; }

        #pragma unroll 1
        for (int t = T - 4; t > -4; t -= 4) {
            int qid[4], aid[4];
            #pragma unroll
            for (int s = 0; s < 4; s++) {
                int tt = t + s;
                qid[s] = (tt >= 0) ? q_ids[b * T + tt] : -1;
                aid[s] = (tt >= 0) ? a_ids[b * T + tt] : -1;
            }
            __syncwarp();                              // prior compute reads done
            for (int e = lane; e < 100; e += 32) {
                float sq = 0.f, sa = 0.f;
                #pragma unroll
                for (int s = 0; s < 4; s++) {
                    if (qid[s] >= 0) {
                        sq += q_emb_gr[(size_t)qid[s] * 100 + e];
                        sa += a_emb_gr[(size_t)aid[s] * 100 + e];
                    }
                }
                int rr = e / 10, cc = e - rr * 10;
                xw[rr * 12 + cc]       = sq * transS[e];
                xw[120 + rr * 12 + cc] = sa;
            }
            __syncwarp();                              // x (=S blocks) visible
            if (active) {
                const float* xb = xw + tbl * 120;
                float u[10], v[10], w1[10], w2[10];
                #pragma unroll
                for (int k = 0; k < 10; k++) { v[k] = 0.f; w2[k] = 0.f; }
                #pragma unroll
                for (int k = 0; k < 10; k++) {
                    float4 r0 = *(const float4*)(xb + k * 12);
                    float4 r1 = *(const float4*)(xb + k * 12 + 4);
                    float4 r2 = *(const float4*)(xb + k * 12 + 8);
                    float xr[10] = {r0.x,r0.y,r0.z,r0.w, r1.x,r1.y,r1.z,r1.w, r2.x,r2.y};
                    float s = 0.f;
                    #pragma unroll
                    for (int c = 0; c < 10; c++) s += xr[c] * Mb[c];
                    u[k] = s;
                    float mtk = Mt[k];
                    #pragma unroll
                    for (int c = 0; c < 10; c++) v[c] += mtk * xr[c];
                }
                #pragma unroll
                for (int k = 0; k < 10; k++) {
                    float4 r0 = *(const float4*)(xb + k * 12);
                    float4 r1 = *(const float4*)(xb + k * 12 + 4);
                    float4 r2 = *(const float4*)(xb + k * 12 + 8);
                    float xr[10] = {r0.x,r0.y,r0.z,r0.w, r1.x,r1.y,r1.z,r1.w, r2.x,r2.y};
                    float s = 0.f;
                    #pragma unroll
                    for (int c = 0; c < 10; c++) s += xr[c] * v[c];
                    w1[k] = s;
                    float uk = u[k];
                    #pragma unroll
                    for (int c = 0; c < 10; c++) w2[c] += uk * xr[c];
                }
                #pragma unroll
                for (int k = 0; k < 10; k++) {
                    Mt[k] = Mt[k] - 2.f * u[k] - 2.f * w1[k];
                    Mb[k] = Mb[k] + 2.f * v[k] - 2.f * w2[k];
                }
            }
        }

        // epilogue: dgr
        if (lane < 10) {
            float Q1[20];
            #pragma unroll
            for (int i = 0; i < 20; i++) Q1[i] = 0.f;
            #pragma unroll
            for (int k = 0; k < 20; k++) {
                float ck = (k < 10) ? Mt[k] : Mb[k - 10];
                const float* yr = YbgT + k * 20;
                float4 y0 = *(const float4*)yr,       y1 = *(const float4*)(yr + 4),
                       y2 = *(const float4*)(yr + 8), y3 = *(const float4*)(yr + 12),
                       y4 = *(const float4*)(yr + 16);
                Q1[0]+=ck*y0.x; Q1[1]+=ck*y0.y; Q1[2]+=ck*y0.z; Q1[3]+=ck*y0.w;
                Q1[4]+=ck*y1.x; Q1[5]+=ck*y1.y; Q1[6]+=ck*y1.z; Q1[7]+=ck*y1.w;
                Q1[8]+=ck*y2.x; Q1[9]+=ck*y2.y; Q1[10]+=ck*y2.z; Q1[11]+=ck*y2.w;
                Q1[12]+=ck*y3.x; Q1[13]+=ck*y3.y; Q1[14]+=ck*y3.z; Q1[15]+=ck*y3.w;
                Q1[16]+=ck*y4.x; Q1[17]+=ck*y4.y; Q1[18]+=ck*y4.z; Q1[19]+=ck*y4.w;
            }
            #pragma unroll
            for (int i = 0; i < 20; i += 4)
                *(float4*)(q1w + j * 20 + i) = make_float4(Q1[i], Q1[i+1], Q1[i+2], Q1[i+3]);
        }
        __syncwarp();
        float s_loc = 0.f;
        if (lane >= 10 && lane < 20) {
            #pragma unroll
            for (int i = 0; i < 10; i++) {
                const float* qc = q1w + i * 20;
                float4 a0 = *(const float4*)qc,       a1 = *(const float4*)(qc + 4),
                       a2 = *(const float4*)(qc + 8), a3 = *(const float4*)(qc + 12),
                       a4 = *(const float4*)(qc + 16);
                float qv[20] = {a0.x,a0.y,a0.z,a0.w, a1.x,a1.y,a1.z,a1.w,
                                a2.x,a2.y,a2.z,a2.w, a3.x,a3.y,a3.z,a3.w,
                                a4.x,a4.y,a4.z,a4.w};
                float d = 0.f;
                #pragma unroll
                for (int k = 0; k < 20; k++) d += qv[k] * ((k < 10) ? Mt[k] : Mb[k - 10]);
                s_loc += d * d;
            }
        }
        #pragma unroll
        for (int o = 16; o; o >>= 1) s_loc += __shfl_xor_sync(0xffffffffu, s_loc, o);
        if (lane == 0) dgr_s = sqrtf(fmaxf(20.f - 2.f * s_loc, 0.f));
    }

    __syncthreads();                                   // dgr_s ready
    if (w == 0 && lane == 0)
        out[b] = -wf[0] * (dspd + dgr_s) + wb[0];
}

// =====================================================================
extern "C" void kernel_launch(void* const* d_in, const int* in_sizes, int n_in,
                              void* d_out, int out_size)
{
    const int*   q_ids      = (const int*)  d_in[0];
    const int*   a_ids      = (const int*)  d_in[1];
    const float* q_emb_spd  = (const float*)d_in[2];
    const float* a_emb_spd  = (const float*)d_in[3];
    const float* ref_params = (const float*)d_in[4];
    const float* bias_spd   = (const float*)d_in[5];
    const float* q_emb_gr   = (const float*)d_in[6];
    const float* a_emb_gr   = (const float*)d_in[7];
    const float* trans_gr   = (const float*)d_in[8];
    const float* bias_gr    = (const float*)d_in[9];
    const float* wf         = (const float*)d_in[10];
    const float* wb         = (const float*)d_in[11];
    float* out = (float*)d_out;

    int B = out_size;
    int T = in_sizes[0] / B;

    precompute_kernel<<<1, 256>>>(ref_params, bias_spd, bias_gr);
    fused_kernel<<<B, 64>>>(q_ids, a_ids, q_emb_spd, a_emb_spd,
                            q_emb_gr, a_emb_gr, trans_gr, wf, wb, out, B, T);
}